// round 2
// baseline (speedup 1.0000x reference)
#include <cuda_runtime.h>
#include <cstdint>

// ---------------------------------------------------------------------------
// HGCNLayer: two-hop mean aggregation over a bipartite graph.
//   rst  = segsum(h_src[edge_src] -> edge_dst) / max(deg_dst,1)
//   bsrc = segsum(rst[edge_dst]   -> edge_src) / max(deg_src,1)   (NORM_2=-1)
// Output layout: [bsrc (n_src x 128) | rst (n_dst x 128)]
// ---------------------------------------------------------------------------

#define D_FEAT 128

// scratch degree counters (no allocation allowed) — referenced ONLY in device code
__device__ int g_deg_dst[1 << 21];
__device__ int g_deg_src[1 << 21];

// --- zero the degree scratch (only the used prefix) ---
__global__ void zero_deg_kernel(int n_src, int n_dst) {
    int i = blockIdx.x * blockDim.x + threadIdx.x;
    if (i < n_dst) g_deg_dst[i] = 0;
    if (i < n_src) g_deg_src[i] = 0;
}

// --- degree counting: one thread per edge, both directions ---
__global__ void degree_kernel(const int* __restrict__ edge_src,
                              const int* __restrict__ edge_dst,
                              int n_edges) {
    int e = blockIdx.x * blockDim.x + threadIdx.x;
    if (e < n_edges) {
        atomicAdd(&g_deg_dst[edge_dst[e]], 1);
        atomicAdd(&g_deg_src[edge_src[e]], 1);
    }
}

// --- scatter-add: warp per edge, float4 per lane, vectorized red.add ---
__global__ void scatter_kernel(const float* __restrict__ feat,
                               const int*   __restrict__ idx_in,
                               const int*   __restrict__ idx_out,
                               float*       __restrict__ out,
                               int n_edges) {
    int gtid  = blockIdx.x * blockDim.x + threadIdx.x;
    int warp  = gtid >> 5;
    int lane  = threadIdx.x & 31;
    int nwarp = (gridDim.x * blockDim.x) >> 5;

    for (int e = warp; e < n_edges; e += nwarp) {
        int s = idx_in[e];   // warp-uniform load (broadcast)
        int d = idx_out[e];
        const float4 v = reinterpret_cast<const float4*>(
                             feat + (size_t)s * D_FEAT)[lane];
        float4* dst = reinterpret_cast<float4*>(
                             out + (size_t)d * D_FEAT) + lane;
        asm volatile("red.global.add.v4.f32 [%0], {%1,%2,%3,%4};"
                     :: "l"(dst), "f"(v.x), "f"(v.y), "f"(v.z), "f"(v.w)
                     : "memory");
    }
}

// --- per-node scaling by 1/max(deg,1): one thread per float4 ---
// Two specializations referencing the __device__ globals directly
// (a __device__ symbol must never be passed as an arg from host code).
__global__ void scale_dst_kernel(float* __restrict__ buf, int n_nodes) {
    int i = blockIdx.x * blockDim.x + threadIdx.x;   // node*32 + vec
    int node = i >> 5;
    if (node >= n_nodes) return;
    int dg = g_deg_dst[node];
    float inv = 1.0f / (float)(dg > 0 ? dg : 1);
    float4* p = reinterpret_cast<float4*>(buf + (size_t)node * D_FEAT) + (i & 31);
    float4 v = *p;
    v.x *= inv; v.y *= inv; v.z *= inv; v.w *= inv;
    *p = v;
}

__global__ void scale_src_kernel(float* __restrict__ buf, int n_nodes) {
    int i = blockIdx.x * blockDim.x + threadIdx.x;
    int node = i >> 5;
    if (node >= n_nodes) return;
    int dg = g_deg_src[node];
    float inv = 1.0f / (float)(dg > 0 ? dg : 1);
    float4* p = reinterpret_cast<float4*>(buf + (size_t)node * D_FEAT) + (i & 31);
    float4 v = *p;
    v.x *= inv; v.y *= inv; v.z *= inv; v.w *= inv;
    *p = v;
}

extern "C" void kernel_launch(void* const* d_in, const int* in_sizes, int n_in,
                              void* d_out, int out_size) {
    const float* h_src    = (const float*)d_in[0];
    const int*   edge_src = (const int*)d_in[1];
    const int*   edge_dst = (const int*)d_in[2];

    const int n_src   = in_sizes[0] / D_FEAT;
    const int n_edges = in_sizes[1];
    const int n_dst   = out_size / D_FEAT - n_src;

    float* bsrc = (float*)d_out;                          // [n_src, 128]
    float* rst  = (float*)d_out + (size_t)n_src * D_FEAT; // [n_dst, 128]

    // 1) zero output accumulators + degree scratch
    cudaMemsetAsync(d_out, 0, (size_t)out_size * sizeof(float));
    {
        int n = (n_src > n_dst ? n_src : n_dst);
        zero_deg_kernel<<<(n + 255) / 256, 256>>>(n_src, n_dst);
    }

    // 2) degrees (both directions)
    degree_kernel<<<(n_edges + 255) / 256, 256>>>(edge_src, edge_dst, n_edges);

    // 3) forward scatter: h_src[edge_src] += into rst[edge_dst]
    {
        const int threads = 256;                 // 8 warps/block
        int blocks = (n_edges + 7) / 8;
        scatter_kernel<<<blocks, threads>>>(h_src, edge_src, edge_dst,
                                            rst, n_edges);
    }

    // 4) rst /= max(deg_dst, 1)
    {
        long long work = (long long)n_dst * 32;
        scale_dst_kernel<<<(int)((work + 255) / 256), 256>>>(rst, n_dst);
    }

    // 5) backward scatter: rst[edge_dst] += into bsrc[edge_src]
    {
        const int threads = 256;
        int blocks = (n_edges + 7) / 8;
        scatter_kernel<<<blocks, threads>>>(rst, edge_dst, edge_src,
                                            bsrc, n_edges);
    }

    // 6) bsrc /= max(deg_src, 1)   (NORM_2 = -1)
    {
        long long work = (long long)n_src * 32;
        scale_src_kernel<<<(int)((work + 255) / 256), 256>>>(bsrc, n_src);
    }
}

// round 3
// speedup vs baseline: 1.0785x; 1.0785x over previous
#include <cuda_runtime.h>
#include <cstdint>

// ---------------------------------------------------------------------------
// HGCNLayer: two-hop mean aggregation over a bipartite graph.
//   rst  = segsum(h_src[edge_src] -> edge_dst) / max(deg_dst,1)
//   bsrc = segsum(rst[edge_dst]   -> edge_src) / max(deg_src,1)   (NORM_2=-1)
// Output layout: [bsrc (n_src x 128) | rst (n_dst x 128)]
//
// Strategy: build CSR in both directions on the fly, then do warp-per-node
// gather-sum (no float atomics, output written exactly once, scale fused).
// ---------------------------------------------------------------------------

#define D_FEAT 128
#define MAXN   (1 << 21)
#define MAXE   (1 << 21)

// index 0 = dst-direction (group edges by dst, store src ids)
// index 1 = src-direction (group edges by src, store dst ids)
__device__ int g_cnt[2][MAXN];       // degree counts, then reused as fill cursors
__device__ int g_off[2][MAXN + 1];   // exclusive offsets
__device__ int g_csr[2][MAXE];       // neighbor ids

// --- zero the count prefix for both directions ---
__global__ void zero_cnt_kernel(int n_dst, int n_src) {
    int i = blockIdx.x * blockDim.x + threadIdx.x;
    if (i < n_dst) g_cnt[0][i] = 0;
    if (i < n_src) g_cnt[1][i] = 0;
}

// --- degree counting: one thread per edge, both directions ---
__global__ void degree_kernel(const int* __restrict__ edge_src,
                              const int* __restrict__ edge_dst,
                              int n_edges) {
    int e = blockIdx.x * blockDim.x + threadIdx.x;
    if (e < n_edges) {
        atomicAdd(&g_cnt[0][edge_dst[e]], 1);
        atomicAdd(&g_cnt[1][edge_src[e]], 1);
    }
}

// --- single-block exclusive scan over g_cnt[which][0..n), writes g_off and
//     resets g_cnt to the offsets (to serve as fill cursors) ---
__global__ void scan_kernel(int which, int n) {
    const int T = 1024;
    __shared__ int sh[T];
    int t = threadIdx.x;
    int* cnt = g_cnt[which];
    int* off = g_off[which];

    int c   = (n + T - 1) / T;          // chunk size per thread
    int beg = t * c;
    int end = beg + c; if (end > n) end = n;
    if (beg > n) beg = n;

    int lsum = 0;
    for (int i = beg; i < end; i++) lsum += cnt[i];

    sh[t] = lsum;
    __syncthreads();
    // Hillis-Steele inclusive scan
    for (int s = 1; s < T; s <<= 1) {
        int v = (t >= s) ? sh[t - s] : 0;
        __syncthreads();
        sh[t] += v;
        __syncthreads();
    }
    int running = sh[t] - lsum;         // exclusive prefix of this thread

    for (int i = beg; i < end; i++) {
        int v = cnt[i];
        off[i] = running;
        cnt[i] = running;               // cursor init
        running += v;
    }
    if (t == T - 1) off[n] = sh[T - 1]; // total
}

// --- bucket fill: scatter neighbor ids into CSR order, both directions ---
__global__ void fill_kernel(const int* __restrict__ edge_src,
                            const int* __restrict__ edge_dst,
                            int n_edges) {
    int e = blockIdx.x * blockDim.x + threadIdx.x;
    if (e < n_edges) {
        int s = edge_src[e];
        int d = edge_dst[e];
        int p = atomicAdd(&g_cnt[0][d], 1);
        g_csr[0][p] = s;
        int q = atomicAdd(&g_cnt[1][s], 1);
        g_csr[1][q] = d;
    }
}

// --- warp-per-node gather-sum with fused 1/max(deg,1) scale ---
__global__ void gather_kernel(int which,
                              const float* __restrict__ feat,
                              float*       __restrict__ out,
                              int n_nodes) {
    int gtid = blockIdx.x * blockDim.x + threadIdx.x;
    int w    = gtid >> 5;               // node id
    int lane = threadIdx.x & 31;
    if (w >= n_nodes) return;

    const int* off = g_off[which];
    const int* csr = g_csr[which];

    int beg = off[w];
    int end = off[w + 1];

    float4 acc = make_float4(0.f, 0.f, 0.f, 0.f);
    int j = beg;
    for (; j + 4 <= end; j += 4) {
        int i0 = csr[j + 0], i1 = csr[j + 1], i2 = csr[j + 2], i3 = csr[j + 3];
        float4 a = __ldg(reinterpret_cast<const float4*>(feat + (size_t)i0 * D_FEAT) + lane);
        float4 b = __ldg(reinterpret_cast<const float4*>(feat + (size_t)i1 * D_FEAT) + lane);
        float4 cc = __ldg(reinterpret_cast<const float4*>(feat + (size_t)i2 * D_FEAT) + lane);
        float4 dd = __ldg(reinterpret_cast<const float4*>(feat + (size_t)i3 * D_FEAT) + lane);
        acc.x += a.x + b.x + cc.x + dd.x;
        acc.y += a.y + b.y + cc.y + dd.y;
        acc.z += a.z + b.z + cc.z + dd.z;
        acc.w += a.w + b.w + cc.w + dd.w;
    }
    for (; j < end; j++) {
        float4 a = __ldg(reinterpret_cast<const float4*>(feat + (size_t)csr[j] * D_FEAT) + lane);
        acc.x += a.x; acc.y += a.y; acc.z += a.z; acc.w += a.w;
    }

    int deg = end - beg;
    float inv = 1.0f / (float)(deg > 0 ? deg : 1);
    acc.x *= inv; acc.y *= inv; acc.z *= inv; acc.w *= inv;
    reinterpret_cast<float4*>(out + (size_t)w * D_FEAT)[lane] = acc;
}

extern "C" void kernel_launch(void* const* d_in, const int* in_sizes, int n_in,
                              void* d_out, int out_size) {
    const float* h_src    = (const float*)d_in[0];
    const int*   edge_src = (const int*)d_in[1];
    const int*   edge_dst = (const int*)d_in[2];

    const int n_src   = in_sizes[0] / D_FEAT;
    const int n_edges = in_sizes[1];
    const int n_dst   = out_size / D_FEAT - n_src;

    float* bsrc = (float*)d_out;                          // [n_src, 128]
    float* rst  = (float*)d_out + (size_t)n_src * D_FEAT; // [n_dst, 128]

    // 1) CSR build
    {
        int n = (n_src > n_dst ? n_src : n_dst);
        zero_cnt_kernel<<<(n + 255) / 256, 256>>>(n_dst, n_src);
    }
    degree_kernel<<<(n_edges + 255) / 256, 256>>>(edge_src, edge_dst, n_edges);
    scan_kernel<<<1, 1024>>>(0, n_dst);
    scan_kernel<<<1, 1024>>>(1, n_src);
    fill_kernel<<<(n_edges + 255) / 256, 256>>>(edge_src, edge_dst, n_edges);

    // 2) forward pass: rst = mean over incoming src rows
    {
        long long thr = (long long)n_dst * 32;
        gather_kernel<<<(int)((thr + 255) / 256), 256>>>(0, h_src, rst, n_dst);
    }

    // 3) backward pass: bsrc = mean over incoming rst rows (NORM_2 = -1)
    {
        long long thr = (long long)n_src * 32;
        gather_kernel<<<(int)((thr + 255) / 256), 256>>>(1, rst, bsrc, n_src);
    }
}

// round 4
// speedup vs baseline: 2.3020x; 2.1345x over previous
#include <cuda_runtime.h>
#include <cstdint>

// ---------------------------------------------------------------------------
// HGCNLayer: two-hop mean aggregation over a bipartite graph.
//   rst  = segsum(h_src[edge_src] -> edge_dst) / max(deg_dst,1)
//   bsrc = segsum(rst[edge_dst]   -> edge_src) / max(deg_src,1)   (NORM_2=-1)
// Output layout: [bsrc (n_src x 128) | rst (n_dst x 128)]
//
// CSR built on the fly (both directions) with a proper two-level parallel
// scan, then warp-per-node gather-sum (no float atomics, fused scale).
// ---------------------------------------------------------------------------

#define D_FEAT 128
#define MAXN   (1 << 21)
#define MAXE   (1 << 21)
#define SCAN_T 1024

// index 0 = dst-direction (group edges by dst, store src ids)
// index 1 = src-direction (group edges by src, store dst ids)
__device__ int g_cnt[2][MAXN];       // degree counts, then reused as fill cursors
__device__ int g_off[2][MAXN + 1];   // exclusive offsets
__device__ int g_csr[2][MAXE];       // neighbor ids
__device__ int g_bsum[2][2048];      // per-block partial sums for the scan

// --- zero the count prefix for both directions ---
__global__ void zero_cnt_kernel(int n_dst, int n_src) {
    int i = blockIdx.x * blockDim.x + threadIdx.x;
    if (i < n_dst) g_cnt[0][i] = 0;
    if (i < n_src) g_cnt[1][i] = 0;
}

// --- degree counting: one thread per edge, both directions ---
__global__ void degree_kernel(const int* __restrict__ edge_src,
                              const int* __restrict__ edge_dst,
                              int n_edges) {
    int e = blockIdx.x * blockDim.x + threadIdx.x;
    if (e < n_edges) {
        atomicAdd(&g_cnt[0][edge_dst[e]], 1);
        atomicAdd(&g_cnt[1][edge_src[e]], 1);
    }
}

// --- scan pass 1: per-block (1024-elem) sums ---
__global__ void scan_pass1(int which, int n) {
    __shared__ int sh[SCAN_T];
    int t = threadIdx.x;
    int i = blockIdx.x * SCAN_T + t;
    sh[t] = (i < n) ? g_cnt[which][i] : 0;
    __syncthreads();
    for (int s = SCAN_T / 2; s > 0; s >>= 1) {
        if (t < s) sh[t] += sh[t + s];
        __syncthreads();
    }
    if (t == 0) g_bsum[which][blockIdx.x] = sh[0];
}

// --- scan pass 2: exclusive scan of block sums (single block, both dirs) ---
// supports up to 1024 blocks per direction (n <= 1M nodes)
__global__ void scan_pass2(int nb0, int nb1) {
    __shared__ int sh[SCAN_T];
    int t = threadIdx.x;
    for (int w = 0; w < 2; w++) {
        int nb = w ? nb1 : nb0;
        int v = (t < nb) ? g_bsum[w][t] : 0;
        sh[t] = v;
        __syncthreads();
        for (int s = 1; s < SCAN_T; s <<= 1) {
            int u = (t >= s) ? sh[t - s] : 0;
            __syncthreads();
            sh[t] += u;
            __syncthreads();
        }
        if (t < nb) g_bsum[w][t] = sh[t] - v;   // exclusive
        __syncthreads();
    }
}

// --- scan pass 3: block-local exclusive scan + block offset; writes off+cursor ---
__global__ void scan_pass3(int which, int n) {
    __shared__ int sh[SCAN_T];
    int t = threadIdx.x;
    int i = blockIdx.x * SCAN_T + t;
    int v = (i < n) ? g_cnt[which][i] : 0;
    sh[t] = v;
    __syncthreads();
    for (int s = 1; s < SCAN_T; s <<= 1) {
        int u = (t >= s) ? sh[t - s] : 0;
        __syncthreads();
        sh[t] += u;
        __syncthreads();
    }
    if (i < n) {
        int ex = sh[t] - v + g_bsum[which][blockIdx.x];
        g_off[which][i] = ex;
        g_cnt[which][i] = ex;                   // fill cursor
        if (i == n - 1) g_off[which][n] = ex + v;
    }
}

// --- bucket fill: scatter neighbor ids into CSR order, both directions ---
__global__ void fill_kernel(const int* __restrict__ edge_src,
                            const int* __restrict__ edge_dst,
                            int n_edges) {
    int e = blockIdx.x * blockDim.x + threadIdx.x;
    if (e < n_edges) {
        int s = edge_src[e];
        int d = edge_dst[e];
        int p = atomicAdd(&g_cnt[0][d], 1);
        g_csr[0][p] = s;
        int q = atomicAdd(&g_cnt[1][s], 1);
        g_csr[1][q] = d;
    }
}

// --- warp-per-node gather-sum with fused 1/max(deg,1) scale ---
__global__ void gather_kernel(int which,
                              const float* __restrict__ feat,
                              float*       __restrict__ out,
                              int n_nodes) {
    int gtid = blockIdx.x * blockDim.x + threadIdx.x;
    int w    = gtid >> 5;               // node id
    int lane = threadIdx.x & 31;
    if (w >= n_nodes) return;

    const int* off = g_off[which];
    const int* csr = g_csr[which];

    int beg = off[w];
    int end = off[w + 1];

    float4 acc = make_float4(0.f, 0.f, 0.f, 0.f);
    int j = beg;
    for (; j + 4 <= end; j += 4) {
        int i0 = csr[j + 0], i1 = csr[j + 1], i2 = csr[j + 2], i3 = csr[j + 3];
        float4 a  = __ldg(reinterpret_cast<const float4*>(feat + (size_t)i0 * D_FEAT) + lane);
        float4 b  = __ldg(reinterpret_cast<const float4*>(feat + (size_t)i1 * D_FEAT) + lane);
        float4 cc = __ldg(reinterpret_cast<const float4*>(feat + (size_t)i2 * D_FEAT) + lane);
        float4 dd = __ldg(reinterpret_cast<const float4*>(feat + (size_t)i3 * D_FEAT) + lane);
        acc.x += a.x + b.x + cc.x + dd.x;
        acc.y += a.y + b.y + cc.y + dd.y;
        acc.z += a.z + b.z + cc.z + dd.z;
        acc.w += a.w + b.w + cc.w + dd.w;
    }
    for (; j < end; j++) {
        float4 a = __ldg(reinterpret_cast<const float4*>(feat + (size_t)csr[j] * D_FEAT) + lane);
        acc.x += a.x; acc.y += a.y; acc.z += a.z; acc.w += a.w;
    }

    int deg = end - beg;
    float inv = 1.0f / (float)(deg > 0 ? deg : 1);
    acc.x *= inv; acc.y *= inv; acc.z *= inv; acc.w *= inv;
    reinterpret_cast<float4*>(out + (size_t)w * D_FEAT)[lane] = acc;
}

extern "C" void kernel_launch(void* const* d_in, const int* in_sizes, int n_in,
                              void* d_out, int out_size) {
    const float* h_src    = (const float*)d_in[0];
    const int*   edge_src = (const int*)d_in[1];
    const int*   edge_dst = (const int*)d_in[2];

    const int n_src   = in_sizes[0] / D_FEAT;
    const int n_edges = in_sizes[1];
    const int n_dst   = out_size / D_FEAT - n_src;

    float* bsrc = (float*)d_out;                          // [n_src, 128]
    float* rst  = (float*)d_out + (size_t)n_src * D_FEAT; // [n_dst, 128]

    const int nb0 = (n_dst + SCAN_T - 1) / SCAN_T;
    const int nb1 = (n_src + SCAN_T - 1) / SCAN_T;

    // 1) CSR build
    {
        int n = (n_src > n_dst ? n_src : n_dst);
        zero_cnt_kernel<<<(n + 255) / 256, 256>>>(n_dst, n_src);
    }
    degree_kernel<<<(n_edges + 255) / 256, 256>>>(edge_src, edge_dst, n_edges);
    scan_pass1<<<nb0, SCAN_T>>>(0, n_dst);
    scan_pass1<<<nb1, SCAN_T>>>(1, n_src);
    scan_pass2<<<1, SCAN_T>>>(nb0, nb1);
    scan_pass3<<<nb0, SCAN_T>>>(0, n_dst);
    scan_pass3<<<nb1, SCAN_T>>>(1, n_src);
    fill_kernel<<<(n_edges + 255) / 256, 256>>>(edge_src, edge_dst, n_edges);

    // 2) forward pass: rst = mean over incoming src rows
    {
        long long thr = (long long)n_dst * 32;
        gather_kernel<<<(int)((thr + 255) / 256), 256>>>(0, h_src, rst, n_dst);
    }

    // 3) backward pass: bsrc = mean over incoming rst rows (NORM_2 = -1)
    {
        long long thr = (long long)n_src * 32;
        gather_kernel<<<(int)((thr + 255) / 256), 256>>>(1, rst, bsrc, n_src);
    }
}